// round 7
// baseline (speedup 1.0000x reference)
#include <cuda_runtime.h>
#include <math.h>

#define NN 50000
#define EE 800000
#define HH 64

// ---------------- device scratch (no allocations allowed) ----------------
__device__ float         g_agg[3 * NN * HH];   // per-relation scatter sums (layers 1,2)
__device__ float         g_agg0[NN * 9];       // layer0: [node][rel][3]
__device__ int           g_cnt[NN * 3];        // per-(node,rel) edge counts
__device__ float         g_inv[NN * 3];        // 1/max(cnt,1)
__device__ unsigned char g_et[EE];             // edge type 0..2
__device__ float         g_h[3 * NN * HH];     // h1,h2,h3
__device__ float         g_pre[NN * HH];       // GEMM pre-activation scratch
__device__ float         g_pab[NN * HH];       // [n][0:32]=h3@Wa+b1, [n][32:64]=h3@Wb

// ---------------- kernel 1: edge type + counts ----------------
__global__ void k_edge_prep(const int* __restrict__ ei, const float* __restrict__ ea) {
    int e = blockIdx.x * blockDim.x + threadIdx.x;
    if (e >= EE) return;
    const float q1 = log1pf(5000.0f);
    const float q2 = log1pf(10000.0f);
    float dist = ea[e * 6];
    int t = (dist > q1) + (dist > q2);
    g_et[e] = (unsigned char)t;
    int d = ei[EE + e];
    atomicAdd(&g_cnt[d * 3 + t], 1);
}

__global__ void k_inv() {
    int i = blockIdx.x * blockDim.x + threadIdx.x;
    if (i >= NN * 3) return;
    g_inv[i] = 1.0f / fmaxf((float)g_cnt[i], 1.0f);
}

// ---------------- layer 0 scatter (K=3) ----------------
__global__ void k_scatter0(const int* __restrict__ ei, const float* __restrict__ x) {
    int e = blockIdx.x * blockDim.x + threadIdx.x;
    if (e >= EE) return;
    int s = ei[e], d = ei[EE + e];
    int r = g_et[e];
    float* dstp = &g_agg0[d * 9 + r * 3];
    atomicAdd(dstp + 0, x[s * 3 + 0]);
    atomicAdd(dstp + 1, x[s * 3 + 1]);
    atomicAdd(dstp + 2, x[s * 3 + 2]);
}

// ---------------- layer 0 node: rgcn + relu + residual(x@res_w) + LN ----------------
__global__ void k_node0(const float* __restrict__ x,
                        const float* __restrict__ w0, const float* __restrict__ root0,
                        const float* __restrict__ b0,
                        const float* __restrict__ resw, const float* __restrict__ resb,
                        const float* __restrict__ gam, const float* __restrict__ bet,
                        float* __restrict__ out) {
    int tid = threadIdx.x;
    int node = blockIdx.x * 4 + (tid >> 6);
    int j = tid & 63;
    if (node >= NN) return;

    float x0 = x[node * 3 + 0], x1 = x[node * 3 + 1], x2 = x[node * 3 + 2];
    float acc = b0[j];
    acc = fmaf(x0, root0[0 * 64 + j], acc);
    acc = fmaf(x1, root0[1 * 64 + j], acc);
    acc = fmaf(x2, root0[2 * 64 + j], acc);
#pragma unroll
    for (int r = 0; r < 3; r++) {
        float cf = g_inv[node * 3 + r];
#pragma unroll
        for (int i = 0; i < 3; i++) {
            float a = g_agg0[node * 9 + r * 3 + i] * cf;
            acc = fmaf(a, w0[(r * 3 + i) * 64 + j], acc);
        }
    }
    float res = resb[j];
    res = fmaf(x0, resw[0 * 64 + j], res);
    res = fmaf(x1, resw[1 * 64 + j], res);
    res = fmaf(x2, resw[2 * 64 + j], res);
    float v = fmaxf(acc, 0.0f) + res;

    // LN over 64-thread group (2 warps)
    float s = v, q = v * v;
#pragma unroll
    for (int off = 16; off > 0; off >>= 1) {
        s += __shfl_xor_sync(0xffffffff, s, off);
        q += __shfl_xor_sync(0xffffffff, q, off);
    }
    __shared__ float sred[8], qred[8];
    int warp = tid >> 5;
    if ((tid & 31) == 0) { sred[warp] = s; qred[warp] = q; }
    __syncthreads();
    int grp = warp >> 1;
    float ts = sred[grp * 2] + sred[grp * 2 + 1];
    float tq = qred[grp * 2] + qred[grp * 2 + 1];
    float mu = ts * (1.0f / 64.0f);
    float var = tq * (1.0f / 64.0f) - mu * mu;
    float rstd = rsqrtf(var + 1e-5f);
    out[node * 64 + j] = (v - mu) * rstd * gam[j] + bet[j];
}

// ---------------- layers 1/2 scatter (K=64): 16 threads/edge, float4 RED ----------------
__global__ void k_scatter(const int* __restrict__ ei, const float* __restrict__ xi) {
    int g = blockIdx.x * blockDim.x + threadIdx.x;
    int e = g >> 4, lane = g & 15;
    if (e >= EE) return;
    int s = ei[e], d = ei[EE + e];
    int r = g_et[e];
    float4 v = ((const float4*)&xi[s * 64])[lane];
    atomicAdd((float4*)&g_agg[(r * NN + d) * 64 + lane * 4], v);
}

// ---------------- tiled GEMM: [64 nodes x 256] @ [256 x 64] ----------------
// A = [xi | agg0*inv0 | agg1*inv1 | agg2*inv2], B = [root ; W0 ; W1 ; W2]
__global__ void k_rgcn_gemm(const float* __restrict__ xi,
                            const float* __restrict__ root, const float* __restrict__ W,
                            const float* __restrict__ bias, float* __restrict__ outp) {
    __shared__ float As[64 * 65];
    __shared__ float Bs[64 * 64];
    int tid = threadIdx.x;
    int n0 = blockIdx.x * 64;
    int tx = tid & 15, ty = tid >> 4;
    float acc[4][4] = {};

    for (int ko = 0; ko < 256; ko += 64) {
#pragma unroll
        for (int t = 0; t < 16; t++) {
            int idx = tid + t * 256;
            int row = idx >> 6, k = idx & 63;
            int n = n0 + row;
            float v = 0.0f;
            if (n < NN) {
                if (ko == 0) v = xi[n * 64 + k];
                else {
                    int r = (ko >> 6) - 1;
                    v = g_agg[(r * NN + n) * 64 + k] * g_inv[n * 3 + r];
                }
            }
            As[row * 65 + k] = v;
            float w;
            if (ko == 0) w = root[row * 64 + k];
            else {
                int r = (ko >> 6) - 1;
                w = W[r * 4096 + row * 64 + k];
            }
            Bs[row * 64 + k] = w;
        }
        __syncthreads();
#pragma unroll 8
        for (int kk = 0; kk < 64; kk++) {
            float a0 = As[(ty * 4 + 0) * 65 + kk];
            float a1 = As[(ty * 4 + 1) * 65 + kk];
            float a2 = As[(ty * 4 + 2) * 65 + kk];
            float a3 = As[(ty * 4 + 3) * 65 + kk];
            float4 b = *(const float4*)&Bs[kk * 64 + tx * 4];
            acc[0][0] = fmaf(a0, b.x, acc[0][0]); acc[0][1] = fmaf(a0, b.y, acc[0][1]);
            acc[0][2] = fmaf(a0, b.z, acc[0][2]); acc[0][3] = fmaf(a0, b.w, acc[0][3]);
            acc[1][0] = fmaf(a1, b.x, acc[1][0]); acc[1][1] = fmaf(a1, b.y, acc[1][1]);
            acc[1][2] = fmaf(a1, b.z, acc[1][2]); acc[1][3] = fmaf(a1, b.w, acc[1][3]);
            acc[2][0] = fmaf(a2, b.x, acc[2][0]); acc[2][1] = fmaf(a2, b.y, acc[2][1]);
            acc[2][2] = fmaf(a2, b.z, acc[2][2]); acc[2][3] = fmaf(a2, b.w, acc[2][3]);
            acc[3][0] = fmaf(a3, b.x, acc[3][0]); acc[3][1] = fmaf(a3, b.y, acc[3][1]);
            acc[3][2] = fmaf(a3, b.z, acc[3][2]); acc[3][3] = fmaf(a3, b.w, acc[3][3]);
        }
        __syncthreads();
    }
    float4 bv = *(const float4*)&bias[tx * 4];
#pragma unroll
    for (int i = 0; i < 4; i++) {
        int n = n0 + ty * 4 + i;
        if (n < NN) {
            float4 o = make_float4(acc[i][0] + bv.x, acc[i][1] + bv.y,
                                   acc[i][2] + bv.z, acc[i][3] + bv.w);
            *(float4*)&outp[n * 64 + tx * 4] = o;
        }
    }
}

// ---------------- relu + residual + LN ----------------
__global__ void k_relu_res_ln(const float* __restrict__ pre, const float* __restrict__ resid,
                              const float* __restrict__ gam, const float* __restrict__ bet,
                              float* __restrict__ out) {
    int tid = threadIdx.x;
    int node = blockIdx.x * 4 + (tid >> 6);
    int j = tid & 63;
    if (node >= NN) return;
    float v = fmaxf(pre[node * 64 + j], 0.0f) + resid[node * 64 + j];
    float s = v, q = v * v;
#pragma unroll
    for (int off = 16; off > 0; off >>= 1) {
        s += __shfl_xor_sync(0xffffffff, s, off);
        q += __shfl_xor_sync(0xffffffff, q, off);
    }
    __shared__ float sred[8], qred[8];
    int warp = tid >> 5;
    if ((tid & 31) == 0) { sred[warp] = s; qred[warp] = q; }
    __syncthreads();
    int grp = warp >> 1;
    float ts = sred[grp * 2] + sred[grp * 2 + 1];
    float tq = qred[grp * 2] + qred[grp * 2 + 1];
    float mu = ts * (1.0f / 64.0f);
    float var = tq * (1.0f / 64.0f) - mu * mu;
    float rstd = rsqrtf(var + 1e-5f);
    out[node * 64 + j] = (v - mu) * rstd * gam[j] + bet[j];
}

// ---------------- per-node decoder precompute: h3@Wa+b1 | h3@Wb ----------------
__global__ void k_pab(const float* __restrict__ h3, const float* __restrict__ dw1,
                      const float* __restrict__ db1, float* __restrict__ pab) {
    int tid = threadIdx.x;
    int node = blockIdx.x * 4 + (tid >> 6);
    int j = tid & 63;
    if (node >= NN) return;
    int jj = j & 31;
    const float* Wp = dw1 + ((j < 32) ? 0 : 64 * 32) + jj;
    float acc = (j < 32) ? db1[jj] : 0.0f;
    const float* hp = &h3[node * 64];
#pragma unroll 8
    for (int k = 0; k < 64; k++)
        acc = fmaf(hp[k], Wp[k * 32], acc);
    pab[node * 64 + j] = acc;
}

// ---------------- edge decoder: warp per 2 edges, grid-stride ----------------
// dec_in @ dec_w1 split: per-node halves precomputed in pab; per-edge terms
// |hs-hd| and hs*hd computed ONCE per k (not per output lane), staged to smem
// as packed float2; {Wc,Wd} interleaved so one LDS.64 feeds 4 FMAs across the
// 2 edges. Second layer maps edge 0 -> lanes 0-15, edge 1 -> lanes 16-31.
__global__ void k_decode(const int* __restrict__ ei, const float* __restrict__ ea,
                         const float* __restrict__ h3, const float* __restrict__ pab,
                         const float* __restrict__ dw1,
                         const float* __restrict__ dw2, const float* __restrict__ db2,
                         const float* __restrict__ dw3, const float* __restrict__ db3,
                         float* __restrict__ out) {
    __shared__ float2 Wcd[64 * 32];        // {Wc,Wd}[k][col], 16KB
    __shared__ float  We[6 * 32], W2[32 * 16], sb2[16];
    __shared__ float2 sf[8][2][64];        // {|s-d|, s*d} per warp/edge/k, 8KB
    __shared__ float  zsh[8][2][33];       // padded: no bank conflict across halves
    int tid = threadIdx.x;
    for (int i = tid; i < 64 * 32; i += 256)
        Wcd[i] = make_float2(dw1[128 * 32 + i], dw1[192 * 32 + i]);
    for (int i = tid; i < 6 * 32; i += 256) We[i] = dw1[256 * 32 + i];
    for (int i = tid; i < 32 * 16; i += 256) W2[i] = dw2[i];
    if (tid < 16) sb2[tid] = db2[tid];
    __syncthreads();

    int warp = tid >> 5, lane = tid & 31;
    int col = lane & 15;
    int eh = lane >> 4;                    // which of the 2 edges this half-warp finishes
    float w3r = dw3[col];
    float b3 = db3[0];
    int base = (blockIdx.x * 8 + warp) * 2;
    int stride = gridDim.x * 8 * 2;

    for (int e0 = base; e0 < EE; e0 += stride) {   // EE even -> e0+1 always valid
        int e1 = e0 + 1;
        int s0 = ei[e0], d0 = ei[EE + e0];
        int s1 = ei[e1], d1 = ei[EE + e1];
        {
            float a  = h3[s0 * 64 + lane],      b  = h3[d0 * 64 + lane];
            float a2 = h3[s0 * 64 + 32 + lane], b2 = h3[d0 * 64 + 32 + lane];
            sf[warp][0][lane]      = make_float2(fabsf(a - b),   a * b);
            sf[warp][0][32 + lane] = make_float2(fabsf(a2 - b2), a2 * b2);
            a  = h3[s1 * 64 + lane];      b  = h3[d1 * 64 + lane];
            a2 = h3[s1 * 64 + 32 + lane]; b2 = h3[d1 * 64 + 32 + lane];
            sf[warp][1][lane]      = make_float2(fabsf(a - b),   a * b);
            sf[warp][1][32 + lane] = make_float2(fabsf(a2 - b2), a2 * b2);
        }
        __syncwarp();

        float acc0 = pab[s0 * 64 + lane] + pab[d0 * 64 + 32 + lane];
        float acc1 = pab[s1 * 64 + lane] + pab[d1 * 64 + 32 + lane];
#pragma unroll
        for (int i = 0; i < 6; i++) {
            float w = We[i * 32 + lane];
            acc0 = fmaf(ea[e0 * 6 + i], w, acc0);
            acc1 = fmaf(ea[e1 * 6 + i], w, acc1);
        }
#pragma unroll 16
        for (int k = 0; k < 64; k++) {
            float2 w  = Wcd[k * 32 + lane];
            float2 f0 = sf[warp][0][k];
            float2 f1 = sf[warp][1][k];
            acc0 = fmaf(f0.x, w.x, acc0);
            acc0 = fmaf(f0.y, w.y, acc0);
            acc1 = fmaf(f1.x, w.x, acc1);
            acc1 = fmaf(f1.y, w.y, acc1);
        }
        zsh[warp][0][lane] = fmaxf(acc0, 0.0f);
        zsh[warp][1][lane] = fmaxf(acc1, 0.0f);
        __syncwarp();

        float a2 = sb2[col];
#pragma unroll 8
        for (int j = 0; j < 32; j++)
            a2 = fmaf(zsh[warp][eh][j], W2[j * 16 + col], a2);
        float o = fmaxf(a2, 0.0f) * w3r;
        o += __shfl_xor_sync(0xffffffff, o, 8);   // xor of bits 0-3 stays within half
        o += __shfl_xor_sync(0xffffffff, o, 4);
        o += __shfl_xor_sync(0xffffffff, o, 2);
        o += __shfl_xor_sync(0xffffffff, o, 1);
        if (col == 0) out[e0 + eh] = o + b3;
        __syncwarp();                              // sf/zsh reuse next iteration
    }
}

// ---------------- host launch ----------------
extern "C" void kernel_launch(void* const* d_in, const int* in_sizes, int n_in,
                              void* d_out, int out_size) {
    const float* x     = (const float*)d_in[0];
    const int*   ei    = (const int*)d_in[1];
    const float* ea    = (const float*)d_in[2];
    const float* w0    = (const float*)d_in[3];
    const float* root0 = (const float*)d_in[4];
    const float* b0    = (const float*)d_in[5];
    const float* w1    = (const float*)d_in[6];
    const float* root1 = (const float*)d_in[7];
    const float* b1    = (const float*)d_in[8];
    const float* w2    = (const float*)d_in[9];
    const float* root2 = (const float*)d_in[10];
    const float* b2    = (const float*)d_in[11];
    const float* lng0  = (const float*)d_in[12];
    const float* lnb0  = (const float*)d_in[13];
    const float* lng1  = (const float*)d_in[14];
    const float* lnb1  = (const float*)d_in[15];
    const float* lng2  = (const float*)d_in[16];
    const float* lnb2  = (const float*)d_in[17];
    const float* resw  = (const float*)d_in[18];
    const float* resb  = (const float*)d_in[19];
    const float* dw1   = (const float*)d_in[20];
    const float* db1   = (const float*)d_in[21];
    const float* dw2   = (const float*)d_in[22];
    const float* db2   = (const float*)d_in[23];
    const float* dw3   = (const float*)d_in[24];
    const float* db3   = (const float*)d_in[25];
    float* out = (float*)d_out;

    void *p_cnt, *p_agg0, *p_agg, *p_h, *p_pre, *p_pab;
    cudaGetSymbolAddress(&p_cnt,  g_cnt);
    cudaGetSymbolAddress(&p_agg0, g_agg0);
    cudaGetSymbolAddress(&p_agg,  g_agg);
    cudaGetSymbolAddress(&p_h,    g_h);
    cudaGetSymbolAddress(&p_pre,  g_pre);
    cudaGetSymbolAddress(&p_pab,  g_pab);
    float* h1  = (float*)p_h;
    float* h2  = h1 + NN * 64;
    float* h3  = h2 + NN * 64;
    float* pre = (float*)p_pre;
    float* pab = (float*)p_pab;

    cudaMemsetAsync(p_cnt,  0, sizeof(int)   * NN * 3);
    cudaMemsetAsync(p_agg0, 0, sizeof(float) * NN * 9);
    cudaMemsetAsync(p_agg,  0, sizeof(float) * 3 * NN * 64);

    k_edge_prep<<<(EE + 255) / 256, 256>>>(ei, ea);
    k_inv<<<(NN * 3 + 255) / 256, 256>>>();

    // layer 0
    k_scatter0<<<(EE + 255) / 256, 256>>>(ei, x);
    k_node0<<<NN / 4, 256>>>(x, w0, root0, b0, resw, resb, lng0, lnb0, h1);

    // layer 1
    k_scatter<<<(EE * 16 + 255) / 256, 256>>>(ei, h1);
    k_rgcn_gemm<<<(NN + 63) / 64, 256>>>(h1, root1, w1, b1, pre);
    k_relu_res_ln<<<NN / 4, 256>>>(pre, h1, lng1, lnb1, h2);

    // layer 2
    cudaMemsetAsync(p_agg, 0, sizeof(float) * 3 * NN * 64);
    k_scatter<<<(EE * 16 + 255) / 256, 256>>>(ei, h2);
    k_rgcn_gemm<<<(NN + 63) / 64, 256>>>(h2, root2, w2, b2, pre);
    k_relu_res_ln<<<NN / 4, 256>>>(pre, h2, lng2, lnb2, h3);

    // decoder
    k_pab<<<NN / 4, 256>>>(h3, dw1, db1, pab);
    k_decode<<<1184, 256>>>(ei, ea, h3, pab, dw1, dw2, db2, dw3, db3, out);
}

// round 8
// speedup vs baseline: 1.3724x; 1.3724x over previous
#include <cuda_runtime.h>
#include <math.h>

#define NN 50000
#define EE 800000
#define HH 64
#define NBINS (NN * 3)          // 150000 (node,rel) bins
#define SCAN_BLOCKS 147         // ceil(150000 / 1024)

typedef unsigned long long ull;

// ---------------- device scratch (no allocations allowed) ----------------
__device__ float         g_agg[3 * NN * HH];   // per-relation gather sums (layers 1,2)
__device__ float         g_agg0[NN * 9];       // layer0: [node][rel][3]
__device__ int           g_cnt[NBINS];         // per-(node,rel) edge counts
__device__ float         g_inv[NBINS];         // 1/max(cnt,1)
__device__ unsigned char g_et[EE];             // edge type 0..2
__device__ int           g_esrc[EE];           // CSR: src node per sorted slot
__device__ int           g_off[NBINS + 1];     // CSR offsets
__device__ int           g_cursor[NBINS];      // fill cursors
__device__ int           g_bsum[256];          // block sums for scan
__device__ float         g_h[3 * NN * HH];     // h1,h2,h3
__device__ float         g_pre[NN * HH];       // GEMM pre-activation scratch
__device__ float         g_pab[NN * HH];       // [n][0:32]=h3@Wa+b1, [n][32:64]=h3@Wb

// ---------------- kernel 1: edge type + counts ----------------
__global__ void k_edge_prep(const int* __restrict__ ei, const float* __restrict__ ea) {
    int e = blockIdx.x * blockDim.x + threadIdx.x;
    if (e >= EE) return;
    const float q1 = log1pf(5000.0f);
    const float q2 = log1pf(10000.0f);
    float dist = ea[e * 6];
    int t = (dist > q1) + (dist > q2);
    g_et[e] = (unsigned char)t;
    int d = ei[EE + e];
    atomicAdd(&g_cnt[d * 3 + t], 1);
}

__global__ void k_inv() {
    int i = blockIdx.x * blockDim.x + threadIdx.x;
    if (i >= NBINS) return;
    g_inv[i] = 1.0f / fmaxf((float)g_cnt[i], 1.0f);
}

// ---------------- CSR scan: 3 kernels ----------------
__global__ void k_scan1() {
    int t = threadIdx.x, blk = blockIdx.x;
    int base = blk * 1024 + t * 4;
    int s = 0;
#pragma unroll
    for (int i = 0; i < 4; i++) {
        int b = base + i;
        if (b < NBINS) s += g_cnt[b];
    }
    __shared__ int sh[256];
    sh[t] = s; __syncthreads();
    for (int off = 128; off > 0; off >>= 1) {
        if (t < off) sh[t] += sh[t + off];
        __syncthreads();
    }
    if (t == 0) g_bsum[blk] = sh[0];
}

__global__ void k_scan2() {
    int t = threadIdx.x;
    int v = (t < SCAN_BLOCKS) ? g_bsum[t] : 0;
    __shared__ int sh[256];
    sh[t] = v; __syncthreads();
    for (int off = 1; off < 256; off <<= 1) {
        int x = (t >= off) ? sh[t - off] : 0;
        __syncthreads();
        sh[t] += x;
        __syncthreads();
    }
    if (t < SCAN_BLOCKS) g_bsum[t] = sh[t] - v;   // exclusive
    if (t == 0) g_off[NBINS] = EE;
}

__global__ void k_scan3() {
    int t = threadIdx.x, blk = blockIdx.x;
    int base = blk * 1024 + t * 4;
    int c[4]; int s = 0;
#pragma unroll
    for (int i = 0; i < 4; i++) {
        int b = base + i;
        c[i] = (b < NBINS) ? g_cnt[b] : 0;
        s += c[i];
    }
    __shared__ int sh[256];
    sh[t] = s; __syncthreads();
    for (int off = 1; off < 256; off <<= 1) {
        int x = (t >= off) ? sh[t - off] : 0;
        __syncthreads();
        sh[t] += x;
        __syncthreads();
    }
    int run = g_bsum[blk] + (sh[t] - s);
#pragma unroll
    for (int i = 0; i < 4; i++) {
        int b = base + i;
        if (b < NBINS) { g_off[b] = run; g_cursor[b] = run; run += c[i]; }
    }
}

__global__ void k_fill(const int* __restrict__ ei) {
    int e = blockIdx.x * blockDim.x + threadIdx.x;
    if (e >= EE) return;
    int s = ei[e], d = ei[EE + e];
    int r = g_et[e];
    int pos = atomicAdd(&g_cursor[d * 3 + r], 1);
    g_esrc[pos] = s;
}

// ---------------- layer 0 scatter (K=3) ----------------
__global__ void k_scatter0(const int* __restrict__ ei, const float* __restrict__ x) {
    int e = blockIdx.x * blockDim.x + threadIdx.x;
    if (e >= EE) return;
    int s = ei[e], d = ei[EE + e];
    int r = g_et[e];
    float* dstp = &g_agg0[d * 9 + r * 3];
    atomicAdd(dstp + 0, x[s * 3 + 0]);
    atomicAdd(dstp + 1, x[s * 3 + 1]);
    atomicAdd(dstp + 2, x[s * 3 + 2]);
}

// ---------------- layer 0 node: rgcn + relu + residual(x@res_w) + LN ----------------
__global__ void k_node0(const float* __restrict__ x,
                        const float* __restrict__ w0, const float* __restrict__ root0,
                        const float* __restrict__ b0,
                        const float* __restrict__ resw, const float* __restrict__ resb,
                        const float* __restrict__ gam, const float* __restrict__ bet,
                        float* __restrict__ out) {
    int tid = threadIdx.x;
    int node = blockIdx.x * 4 + (tid >> 6);
    int j = tid & 63;
    if (node >= NN) return;

    float x0 = x[node * 3 + 0], x1 = x[node * 3 + 1], x2 = x[node * 3 + 2];
    float acc = b0[j];
    acc = fmaf(x0, root0[0 * 64 + j], acc);
    acc = fmaf(x1, root0[1 * 64 + j], acc);
    acc = fmaf(x2, root0[2 * 64 + j], acc);
#pragma unroll
    for (int r = 0; r < 3; r++) {
        float cf = g_inv[node * 3 + r];
#pragma unroll
        for (int i = 0; i < 3; i++) {
            float a = g_agg0[node * 9 + r * 3 + i] * cf;
            acc = fmaf(a, w0[(r * 3 + i) * 64 + j], acc);
        }
    }
    float res = resb[j];
    res = fmaf(x0, resw[0 * 64 + j], res);
    res = fmaf(x1, resw[1 * 64 + j], res);
    res = fmaf(x2, resw[2 * 64 + j], res);
    float v = fmaxf(acc, 0.0f) + res;

    float s = v, q = v * v;
#pragma unroll
    for (int off = 16; off > 0; off >>= 1) {
        s += __shfl_xor_sync(0xffffffff, s, off);
        q += __shfl_xor_sync(0xffffffff, q, off);
    }
    __shared__ float sred[8], qred[8];
    int warp = tid >> 5;
    if ((tid & 31) == 0) { sred[warp] = s; qred[warp] = q; }
    __syncthreads();
    int grp = warp >> 1;
    float ts = sred[grp * 2] + sred[grp * 2 + 1];
    float tq = qred[grp * 2] + qred[grp * 2 + 1];
    float mu = ts * (1.0f / 64.0f);
    float var = tq * (1.0f / 64.0f) - mu * mu;
    float rstd = rsqrtf(var + 1e-5f);
    out[node * 64 + j] = (v - mu) * rstd * gam[j] + bet[j];
}

// ---------------- layers 1/2 gather-aggregate via CSR (no atomics) ----------------
__global__ void k_aggregate(const float* __restrict__ h) {
    int tid = threadIdx.x;
    int node = blockIdx.x * 4 + (tid >> 6);
    int j = tid & 63;
    if (node >= NN) return;
#pragma unroll
    for (int r = 0; r < 3; r++) {
        int bin = node * 3 + r;
        int a = g_off[bin], b = g_off[bin + 1];
        float acc = 0.0f;
        for (int e = a; e < b; e++) {
            int s = g_esrc[e];
            acc += h[s * 64 + j];
        }
        g_agg[(r * NN + node) * 64 + j] = acc;   // raw sum; GEMM applies inv
    }
}

// ---------------- tiled GEMM: [64 nodes x 256] @ [256 x 64] ----------------
__global__ void k_rgcn_gemm(const float* __restrict__ xi,
                            const float* __restrict__ root, const float* __restrict__ W,
                            const float* __restrict__ bias, float* __restrict__ outp) {
    __shared__ float As[64 * 65];
    __shared__ float Bs[64 * 64];
    int tid = threadIdx.x;
    int n0 = blockIdx.x * 64;
    int tx = tid & 15, ty = tid >> 4;
    float acc[4][4] = {};

    for (int ko = 0; ko < 256; ko += 64) {
#pragma unroll
        for (int t = 0; t < 16; t++) {
            int idx = tid + t * 256;
            int row = idx >> 6, k = idx & 63;
            int n = n0 + row;
            float v = 0.0f;
            if (n < NN) {
                if (ko == 0) v = xi[n * 64 + k];
                else {
                    int r = (ko >> 6) - 1;
                    v = g_agg[(r * NN + n) * 64 + k] * g_inv[n * 3 + r];
                }
            }
            As[row * 65 + k] = v;
            float w;
            if (ko == 0) w = root[row * 64 + k];
            else {
                int r = (ko >> 6) - 1;
                w = W[r * 4096 + row * 64 + k];
            }
            Bs[row * 64 + k] = w;
        }
        __syncthreads();
#pragma unroll 8
        for (int kk = 0; kk < 64; kk++) {
            float a0 = As[(ty * 4 + 0) * 65 + kk];
            float a1 = As[(ty * 4 + 1) * 65 + kk];
            float a2 = As[(ty * 4 + 2) * 65 + kk];
            float a3 = As[(ty * 4 + 3) * 65 + kk];
            float4 b = *(const float4*)&Bs[kk * 64 + tx * 4];
            acc[0][0] = fmaf(a0, b.x, acc[0][0]); acc[0][1] = fmaf(a0, b.y, acc[0][1]);
            acc[0][2] = fmaf(a0, b.z, acc[0][2]); acc[0][3] = fmaf(a0, b.w, acc[0][3]);
            acc[1][0] = fmaf(a1, b.x, acc[1][0]); acc[1][1] = fmaf(a1, b.y, acc[1][1]);
            acc[1][2] = fmaf(a1, b.z, acc[1][2]); acc[1][3] = fmaf(a1, b.w, acc[1][3]);
            acc[2][0] = fmaf(a2, b.x, acc[2][0]); acc[2][1] = fmaf(a2, b.y, acc[2][1]);
            acc[2][2] = fmaf(a2, b.z, acc[2][2]); acc[2][3] = fmaf(a2, b.w, acc[2][3]);
            acc[3][0] = fmaf(a3, b.x, acc[3][0]); acc[3][1] = fmaf(a3, b.y, acc[3][1]);
            acc[3][2] = fmaf(a3, b.z, acc[3][2]); acc[3][3] = fmaf(a3, b.w, acc[3][3]);
        }
        __syncthreads();
    }
    float4 bv = *(const float4*)&bias[tx * 4];
#pragma unroll
    for (int i = 0; i < 4; i++) {
        int n = n0 + ty * 4 + i;
        if (n < NN) {
            float4 o = make_float4(acc[i][0] + bv.x, acc[i][1] + bv.y,
                                   acc[i][2] + bv.z, acc[i][3] + bv.w);
            *(float4*)&outp[n * 64 + tx * 4] = o;
        }
    }
}

// ---------------- relu + residual + LN ----------------
__global__ void k_relu_res_ln(const float* __restrict__ pre, const float* __restrict__ resid,
                              const float* __restrict__ gam, const float* __restrict__ bet,
                              float* __restrict__ out) {
    int tid = threadIdx.x;
    int node = blockIdx.x * 4 + (tid >> 6);
    int j = tid & 63;
    if (node >= NN) return;
    float v = fmaxf(pre[node * 64 + j], 0.0f) + resid[node * 64 + j];
    float s = v, q = v * v;
#pragma unroll
    for (int off = 16; off > 0; off >>= 1) {
        s += __shfl_xor_sync(0xffffffff, s, off);
        q += __shfl_xor_sync(0xffffffff, q, off);
    }
    __shared__ float sred[8], qred[8];
    int warp = tid >> 5;
    if ((tid & 31) == 0) { sred[warp] = s; qred[warp] = q; }
    __syncthreads();
    int grp = warp >> 1;
    float ts = sred[grp * 2] + sred[grp * 2 + 1];
    float tq = qred[grp * 2] + qred[grp * 2 + 1];
    float mu = ts * (1.0f / 64.0f);
    float var = tq * (1.0f / 64.0f) - mu * mu;
    float rstd = rsqrtf(var + 1e-5f);
    out[node * 64 + j] = (v - mu) * rstd * gam[j] + bet[j];
}

// ---------------- pab as tiled GEMM: [50K x 64] @ [64 x 64] ----------------
// B column j<32 -> Wa = dw1 rows 0..63; j>=32 -> Wb = dw1 rows 64..127
__global__ void k_pab2(const float* __restrict__ h3, const float* __restrict__ dw1,
                       const float* __restrict__ db1, float* __restrict__ pab) {
    __shared__ float As[64 * 65];
    __shared__ float Bs[64 * 64];
    int tid = threadIdx.x;
    int n0 = blockIdx.x * 64;
    int tx = tid & 15, ty = tid >> 4;
    float acc[4][4] = {};
#pragma unroll
    for (int t = 0; t < 16; t++) {
        int idx = tid + t * 256;
        int row = idx >> 6, k = idx & 63;
        int n = n0 + row;
        As[row * 65 + k] = (n < NN) ? h3[n * 64 + k] : 0.0f;
        Bs[row * 64 + k] = (k < 32) ? dw1[row * 32 + k] : dw1[(64 + row) * 32 + (k - 32)];
    }
    __syncthreads();
#pragma unroll 8
    for (int kk = 0; kk < 64; kk++) {
        float a0 = As[(ty * 4 + 0) * 65 + kk];
        float a1 = As[(ty * 4 + 1) * 65 + kk];
        float a2 = As[(ty * 4 + 2) * 65 + kk];
        float a3 = As[(ty * 4 + 3) * 65 + kk];
        float4 b = *(const float4*)&Bs[kk * 64 + tx * 4];
        acc[0][0] = fmaf(a0, b.x, acc[0][0]); acc[0][1] = fmaf(a0, b.y, acc[0][1]);
        acc[0][2] = fmaf(a0, b.z, acc[0][2]); acc[0][3] = fmaf(a0, b.w, acc[0][3]);
        acc[1][0] = fmaf(a1, b.x, acc[1][0]); acc[1][1] = fmaf(a1, b.y, acc[1][1]);
        acc[1][2] = fmaf(a1, b.z, acc[1][2]); acc[1][3] = fmaf(a1, b.w, acc[1][3]);
        acc[2][0] = fmaf(a2, b.x, acc[2][0]); acc[2][1] = fmaf(a2, b.y, acc[2][1]);
        acc[2][2] = fmaf(a2, b.z, acc[2][2]); acc[2][3] = fmaf(a2, b.w, acc[2][3]);
        acc[3][0] = fmaf(a3, b.x, acc[3][0]); acc[3][1] = fmaf(a3, b.y, acc[3][1]);
        acc[3][2] = fmaf(a3, b.z, acc[3][2]); acc[3][3] = fmaf(a3, b.w, acc[3][3]);
    }
    float4 bv = make_float4(0.f, 0.f, 0.f, 0.f);
    if (tx < 8) bv = *(const float4*)&db1[tx * 4];
#pragma unroll
    for (int i = 0; i < 4; i++) {
        int n = n0 + ty * 4 + i;
        if (n < NN) {
            float4 o = make_float4(acc[i][0] + bv.x, acc[i][1] + bv.y,
                                   acc[i][2] + bv.z, acc[i][3] + bv.w);
            *(float4*)&pab[n * 64 + tx * 4] = o;
        }
    }
}

// ---------------- decoder: block-level GEMM over 64-edge tiles ----------------
// smem carve (floats): Bs[128*32] | F_T[128*66] | zS[32*66] | W2[512] | We[192]
//                      | eS[384] | sIdx[64] dIdx[64] (ints)
#define DEC_SMEM_FLOATS (4096 + 8448 + 2112 + 512 + 192 + 384)
#define DEC_SMEM_BYTES  (DEC_SMEM_FLOATS * 4 + 128 * 4)

__global__ void k_decode_gemm(const int* __restrict__ ei, const float* __restrict__ ea,
                              const float* __restrict__ h3, const float* __restrict__ pab,
                              const float* __restrict__ dw1,
                              const float* __restrict__ dw2, const float* __restrict__ db2,
                              const float* __restrict__ dw3, const float* __restrict__ db3,
                              float* __restrict__ out) {
    extern __shared__ float smf[];
    float* Bs  = smf;               // [128][32] = dw1 rows 128..255
    float* F_T = Bs + 4096;         // [128][66] features^T
    float* zS  = F_T + 8448;        // [32][66]  z^T
    float* W2  = zS + 2112;         // [32][16]
    float* Wes = W2 + 512;          // [6][32]
    float* eS  = Wes + 192;         // [64][6]
    int* sIdx  = (int*)(eS + 384);  // [64]
    int* dIdx  = sIdx + 64;         // [64]

    int tid = threadIdx.x;
    for (int i = tid; i < 4096; i += 256) Bs[i] = dw1[128 * 32 + i];
    for (int i = tid; i < 512; i += 256) W2[i] = dw2[i];
    for (int i = tid; i < 192; i += 256) Wes[i] = dw1[256 * 32 + i];

    // per-thread constants
    int kb = tid & 63, gb = tid >> 6;          // build phase
    int tx = tid & 15, ty = tid >> 4;          // layer1 tiling
    int c = 2 * tx, ty4 = ty * 4;
    int tx2 = tid & 7, ty2 = tid >> 3;         // layer2 tiling
    int c2 = 2 * tx2;
    float b2x = db2[c2], b2y = db2[c2 + 1];
    ull B2X, B2Y;
    asm("mov.b64 %0, {%1, %1};" : "=l"(B2X) : "f"(b2x));
    asm("mov.b64 %0, {%1, %1};" : "=l"(B2Y) : "f"(b2y));
    float w3x = dw3[c2], w3y = dw3[c2 + 1];
    float bias3 = db3[0];
    __syncthreads();

    for (int t = blockIdx.x; t < EE / 64; t += gridDim.x) {
        int e0 = t * 64;
        if (tid < 64) { sIdx[tid] = ei[e0 + tid]; dIdx[tid] = ei[EE + e0 + tid]; }
        for (int i = tid; i < 384; i += 256) eS[i] = ea[e0 * 6 + i];
        __syncthreads();

        // ---- build F_T: k<64 -> |hs-hd|, k>=64 -> hs*hd ----
#pragma unroll 4
        for (int p = 0; p < 16; p++) {
            int eL = p * 4 + gb;
            int sm = sIdx[eL], dm = dIdx[eL];
            float a = h3[sm * 64 + kb], b = h3[dm * 64 + kb];
            F_T[kb * 66 + eL]        = fabsf(a - b);
            F_T[(64 + kb) * 66 + eL] = a * b;
        }
        __syncthreads();

        // ---- layer 1: [64 x 128] @ [128 x 32] + pab + ea terms ----
        float initv[4][2];
#pragma unroll
        for (int i = 0; i < 4; i++) {
            int m = ty4 + i;
            int sm = sIdx[m], dm = dIdx[m];
            float2 pa = *(const float2*)&pab[sm * 64 + c];
            float2 pb = *(const float2*)&pab[dm * 64 + 32 + c];
            float v0 = pa.x + pb.x, v1 = pa.y + pb.y;
#pragma unroll
            for (int q = 0; q < 6; q++) {
                float eq = eS[m * 6 + q];
                float2 w = *(const float2*)&Wes[q * 32 + c];
                v0 = fmaf(eq, w.x, v0);
                v1 = fmaf(eq, w.y, v1);
            }
            initv[i][0] = v0; initv[i][1] = v1;
        }
        ull A00, A01, A10, A11;
        asm("mov.b64 %0, {%1, %2};" : "=l"(A00) : "f"(initv[0][0]), "f"(initv[1][0]));
        asm("mov.b64 %0, {%1, %2};" : "=l"(A01) : "f"(initv[0][1]), "f"(initv[1][1]));
        asm("mov.b64 %0, {%1, %2};" : "=l"(A10) : "f"(initv[2][0]), "f"(initv[3][0]));
        asm("mov.b64 %0, {%1, %2};" : "=l"(A11) : "f"(initv[2][1]), "f"(initv[3][1]));

#pragma unroll 8
        for (int kk = 0; kk < 128; kk++) {
            ull a01 = *(const ull*)&F_T[kk * 66 + ty4];
            ull a23 = *(const ull*)&F_T[kk * 66 + ty4 + 2];
            float2 b = *(const float2*)&Bs[kk * 32 + c];
            ull bx, by;
            asm("mov.b64 %0, {%1, %1};" : "=l"(bx) : "f"(b.x));
            asm("mov.b64 %0, {%1, %1};" : "=l"(by) : "f"(b.y));
            asm("fma.rn.f32x2 %0, %1, %2, %0;" : "+l"(A00) : "l"(a01), "l"(bx));
            asm("fma.rn.f32x2 %0, %1, %2, %0;" : "+l"(A01) : "l"(a01), "l"(by));
            asm("fma.rn.f32x2 %0, %1, %2, %0;" : "+l"(A10) : "l"(a23), "l"(bx));
            asm("fma.rn.f32x2 %0, %1, %2, %0;" : "+l"(A11) : "l"(a23), "l"(by));
        }
        {
            float u0, u1;
            asm("mov.b64 {%0, %1}, %2;" : "=f"(u0), "=f"(u1) : "l"(A00));
            *(float2*)&zS[c * 66 + ty4] = make_float2(fmaxf(u0, 0.f), fmaxf(u1, 0.f));
            asm("mov.b64 {%0, %1}, %2;" : "=f"(u0), "=f"(u1) : "l"(A10));
            *(float2*)&zS[c * 66 + ty4 + 2] = make_float2(fmaxf(u0, 0.f), fmaxf(u1, 0.f));
            asm("mov.b64 {%0, %1}, %2;" : "=f"(u0), "=f"(u1) : "l"(A01));
            *(float2*)&zS[(c + 1) * 66 + ty4] = make_float2(fmaxf(u0, 0.f), fmaxf(u1, 0.f));
            asm("mov.b64 {%0, %1}, %2;" : "=f"(u0), "=f"(u1) : "l"(A11));
            *(float2*)&zS[(c + 1) * 66 + ty4 + 2] = make_float2(fmaxf(u0, 0.f), fmaxf(u1, 0.f));
        }
        __syncthreads();

        // ---- layer 2: [64 x 32] @ [32 x 16], edge pair (2*ty2, 2*ty2+1) ----
        ull Z0 = B2X, Z1 = B2Y;
#pragma unroll 8
        for (int kk = 0; kk < 32; kk++) {
            ull zp = *(const ull*)&zS[kk * 66 + 2 * ty2];
            float2 w = *(const float2*)&W2[kk * 16 + c2];
            ull wx, wy;
            asm("mov.b64 %0, {%1, %1};" : "=l"(wx) : "f"(w.x));
            asm("mov.b64 %0, {%1, %1};" : "=l"(wy) : "f"(w.y));
            asm("fma.rn.f32x2 %0, %1, %2, %0;" : "+l"(Z0) : "l"(zp), "l"(wx));
            asm("fma.rn.f32x2 %0, %1, %2, %0;" : "+l"(Z1) : "l"(zp), "l"(wy));
        }
        float q00, q10, q01, q11;
        asm("mov.b64 {%0, %1}, %2;" : "=f"(q00), "=f"(q10) : "l"(Z0));  // col c2
        asm("mov.b64 {%0, %1}, %2;" : "=f"(q01), "=f"(q11) : "l"(Z1));  // col c2+1
        float o0 = fmaxf(q00, 0.f) * w3x + fmaxf(q01, 0.f) * w3y;  // edge 2*ty2
        float o1 = fmaxf(q10, 0.f) * w3x + fmaxf(q11, 0.f) * w3y;  // edge 2*ty2+1
        o0 += __shfl_xor_sync(0xffffffff, o0, 4);
        o0 += __shfl_xor_sync(0xffffffff, o0, 2);
        o0 += __shfl_xor_sync(0xffffffff, o0, 1);
        o1 += __shfl_xor_sync(0xffffffff, o1, 4);
        o1 += __shfl_xor_sync(0xffffffff, o1, 2);
        o1 += __shfl_xor_sync(0xffffffff, o1, 1);
        if (tx2 == 0) {
            out[e0 + 2 * ty2]     = o0 + bias3;
            out[e0 + 2 * ty2 + 1] = o1 + bias3;
        }
        __syncthreads();
    }
}

// ---------------- host launch ----------------
extern "C" void kernel_launch(void* const* d_in, const int* in_sizes, int n_in,
                              void* d_out, int out_size) {
    const float* x     = (const float*)d_in[0];
    const int*   ei    = (const int*)d_in[1];
    const float* ea    = (const float*)d_in[2];
    const float* w0    = (const float*)d_in[3];
    const float* root0 = (const float*)d_in[4];
    const float* b0    = (const float*)d_in[5];
    const float* w1    = (const float*)d_in[6];
    const float* root1 = (const float*)d_in[7];
    const float* b1    = (const float*)d_in[8];
    const float* w2    = (const float*)d_in[9];
    const float* root2 = (const float*)d_in[10];
    const float* b2    = (const float*)d_in[11];
    const float* lng0  = (const float*)d_in[12];
    const float* lnb0  = (const float*)d_in[13];
    const float* lng1  = (const float*)d_in[14];
    const float* lnb1  = (const float*)d_in[15];
    const float* lng2  = (const float*)d_in[16];
    const float* lnb2  = (const float*)d_in[17];
    const float* resw  = (const float*)d_in[18];
    const float* resb  = (const float*)d_in[19];
    const float* dw1   = (const float*)d_in[20];
    const float* db1   = (const float*)d_in[21];
    const float* dw2   = (const float*)d_in[22];
    const float* db2   = (const float*)d_in[23];
    const float* dw3   = (const float*)d_in[24];
    const float* db3   = (const float*)d_in[25];
    float* out = (float*)d_out;

    static int configured = 0;
    if (!configured) {
        cudaFuncSetAttribute(k_decode_gemm,
                             cudaFuncAttributeMaxDynamicSharedMemorySize, DEC_SMEM_BYTES);
        configured = 1;
    }

    void *p_cnt, *p_agg0, *p_h, *p_pre, *p_pab;
    cudaGetSymbolAddress(&p_cnt,  g_cnt);
    cudaGetSymbolAddress(&p_agg0, g_agg0);
    cudaGetSymbolAddress(&p_h,    g_h);
    cudaGetSymbolAddress(&p_pre,  g_pre);
    cudaGetSymbolAddress(&p_pab,  g_pab);
    float* h1  = (float*)p_h;
    float* h2  = h1 + NN * 64;
    float* h3  = h2 + NN * 64;
    float* pre = (float*)p_pre;
    float* pab = (float*)p_pab;

    cudaMemsetAsync(p_cnt,  0, sizeof(int)   * NBINS);
    cudaMemsetAsync(p_agg0, 0, sizeof(float) * NN * 9);

    k_edge_prep<<<(EE + 255) / 256, 256>>>(ei, ea);
    k_inv<<<(NBINS + 255) / 256, 256>>>();

    // CSR build
    k_scan1<<<SCAN_BLOCKS, 256>>>();
    k_scan2<<<1, 256>>>();
    k_scan3<<<SCAN_BLOCKS, 256>>>();
    k_fill<<<(EE + 255) / 256, 256>>>(ei);

    // layer 0
    k_scatter0<<<(EE + 255) / 256, 256>>>(ei, x);
    k_node0<<<NN / 4, 256>>>(x, w0, root0, b0, resw, resb, lng0, lnb0, h1);

    // layer 1
    k_aggregate<<<NN / 4, 256>>>(h1);
    k_rgcn_gemm<<<(NN + 63) / 64, 256>>>(h1, root1, w1, b1, pre);
    k_relu_res_ln<<<NN / 4, 256>>>(pre, h1, lng1, lnb1, h2);

    // layer 2
    k_aggregate<<<NN / 4, 256>>>(h2);
    k_rgcn_gemm<<<(NN + 63) / 64, 256>>>(h2, root2, w2, b2, pre);
    k_relu_res_ln<<<NN / 4, 256>>>(pre, h2, lng2, lnb2, h3);

    // decoder
    k_pab2<<<(NN + 63) / 64, 256>>>(h3, dw1, db1, pab);
    k_decode_gemm<<<444, 256, DEC_SMEM_BYTES>>>(ei, ea, h3, pab, dw1, dw2, db2, dw3, db3, out);
}